// round 10
// baseline (speedup 1.0000x reference)
#include <cuda_runtime.h>

#define B    512
#define T    200
#define SI   100
#define DI   68
#define HS   256
#define HD   128
#define DTOT 512
#define NB   4           // sequences per RNN CTA (both dirs) -> 128 CTAs

typedef unsigned long long u64;

__device__ __forceinline__ u64 ffma2(u64 a, u64 b, u64 c) {
    u64 d;
    asm("fma.rn.f32x2 %0, %1, %2, %3;" : "=l"(d) : "l"(a), "l"(b), "l"(c));
    return d;
}
__device__ __forceinline__ u64 pack2(float lo, float hi) {
    u64 d;
    asm("mov.b64 %0, {%1, %2};" : "=l"(d) : "f"(lo), "f"(hi));
    return d;
}
__device__ __forceinline__ float2 unpack2(u64 v) {
    float2 r;
    asm("mov.b64 {%0, %1}, %2;" : "=f"(r.x), "=f"(r.y) : "l"(v));
    return r;
}
__device__ __forceinline__ void barsync(int id, int n) {
    asm volatile("bar.sync %0, %1;" :: "r"(id), "r"(n) : "memory");
}

// Scratch (module scope, allocation-free)
__device__ float g_xw[2][B*T*HD];
__device__ float g_static[B];

// ---------------------------------------------------------------------------
// Kernel A: static MLP + routed static dot. 128 CTAs x 4 rows.
// 4 independent FFMA2 chains per thread (k even/odd split) to cover FMA lat.
// ---------------------------------------------------------------------------
#define SROWS 4
#define S1P   8
#define WTP2  258
#define STATIC_SMEM ((SI*S1P + HS*S1P + 128*WTP2 + 32) * 4)

__global__ __launch_bounds__(256, 1) void static_kernel(
    const float* __restrict__ xs, const int* __restrict__ order,
    const float* __restrict__ w1, const float* __restrict__ b1,
    const float* __restrict__ w2, const float* __restrict__ b2,
    const float* __restrict__ nw, const float* __restrict__ nbias)
{
    extern __shared__ float smem[];
    float* xs_t = smem;                       // [SI][S1P]
    float* s1_t = smem + SI*S1P;              // [HS][S1P]
    float* wt   = smem + SI*S1P + HS*S1P;     // [128][WTP2]
    float* red  = wt + 128*WTP2;              // [2][SROWS]

    int tid = threadIdx.x;
    int b0  = blockIdx.x * SROWS;
    int mg  = tid >> 5, ng = tid & 31;
    int row = mg & 3, jh = mg >> 2;

    for (int i = tid; i < SROWS*SI; i += 256) {
        int r = i / SI, k = i % SI;
        xs_t[k*S1P + r] = xs[(b0 + r)*SI + k];
    }
    for (int i = tid; i < HS*(SI/4); i += 256) {
        int o = i / (SI/4), kq = i % (SI/4);
        float4 v = *(const float4*)(w1 + o*SI + kq*4);
        int k0 = kq*4;
        wt[(k0+0)*WTP2 + o] = v.x;
        wt[(k0+1)*WTP2 + o] = v.y;
        wt[(k0+2)*WTP2 + o] = v.z;
        wt[(k0+3)*WTP2 + o] = v.w;
    }
    __syncthreads();

    float2 bb1[2], bb2[2];
    #pragma unroll
    for (int jj = 0; jj < 2; jj++) {
        int oj = 2*ng + 128*jh + 64*jj;
        bb1[jj] = *(const float2*)&b1[oj];
        bb2[jj] = *(const float2*)&b2[oj];
    }

    // GEMM1: 4 chains (2 outs x 2 k-phases)
    {
        u64 acc[2][2] = {{0ull,0ull},{0ull,0ull}};
        #pragma unroll 8
        for (int k = 0; k < SI; k++) {
            float a = xs_t[k*S1P + row];
            u64 p = pack2(a, a);
            const float* wrow = &wt[k*WTP2 + 2*ng + 128*jh];
            int ph = k & 1;
            acc[ph][0] = ffma2(p, *(const u64*)(wrow),      acc[ph][0]);
            acc[ph][1] = ffma2(p, *(const u64*)(wrow + 64), acc[ph][1]);
        }
        __syncthreads();
        #pragma unroll
        for (int jj = 0; jj < 2; jj++) {
            float2 f0 = unpack2(acc[0][jj]);
            float2 f1 = unpack2(acc[1][jj]);
            int oj = 2*ng + 128*jh + 64*jj;
            s1_t[oj*S1P     + row] = fmaxf(f0.x + f1.x + bb1[jj].x, 0.f);
            s1_t[(oj+1)*S1P + row] = fmaxf(f0.y + f1.y + bb1[jj].y, 0.f);
        }
    }

    // GEMM2 (k=HS in 2 halves): 4 chains
    u64 acc2[2][2] = {{0ull,0ull},{0ull,0ull}};
    #pragma unroll 1
    for (int p = 0; p < 2; p++) {
        __syncthreads();
        #pragma unroll
        for (int it = 0; it < 32; it++) {
            int i  = tid + it*256;
            int o  = i >> 5, kq = i & 31;
            float4 v = *(const float4*)(w2 + o*HS + p*128 + kq*4);
            int k0 = kq*4;
            wt[(k0+0)*WTP2 + o] = v.x;
            wt[(k0+1)*WTP2 + o] = v.y;
            wt[(k0+2)*WTP2 + o] = v.z;
            wt[(k0+3)*WTP2 + o] = v.w;
        }
        __syncthreads();

        #pragma unroll 8
        for (int k = 0; k < 128; k++) {
            float a = s1_t[(p*128 + k)*S1P + row];
            u64 pk = pack2(a, a);
            const float* wrow = &wt[k*WTP2 + 2*ng + 128*jh];
            int ph = k & 1;
            acc2[ph][0] = ffma2(pk, *(const u64*)(wrow),      acc2[ph][0]);
            acc2[ph][1] = ffma2(pk, *(const u64*)(wrow + 64), acc2[ph][1]);
        }
    }

    // epilogue: relu + routed static dot
    {
        int n = order[b0 + row];
        float part = 0.f;
        #pragma unroll
        for (int jj = 0; jj < 2; jj++) {
            int oj = 2*ng + 128*jh + 64*jj;
            float2 f0 = unpack2(acc2[0][jj]);
            float2 f1 = unpack2(acc2[1][jj]);
            float2 nv = *(const float2*)&nw[(long)n*DTOT + oj];
            part += fmaxf(f0.x + f1.x + bb2[jj].x, 0.f)*nv.x
                  + fmaxf(f0.y + f1.y + bb2[jj].y, 0.f)*nv.y;
        }
        part += __shfl_xor_sync(0xffffffffu, part, 1);
        part += __shfl_xor_sync(0xffffffffu, part, 2);
        part += __shfl_xor_sync(0xffffffffu, part, 4);
        part += __shfl_xor_sync(0xffffffffu, part, 8);
        part += __shfl_xor_sync(0xffffffffu, part, 16);
        if (ng == 0) red[jh*SROWS + row] = part;
    }
    __syncthreads();
    if (tid < SROWS)
        g_static[b0 + tid] = red[tid] + red[SROWS + tid] + nbias[order[b0 + tid]];
}

// ---------------------------------------------------------------------------
// Kernel B: persistent fused projection (stage1 dyn-proj + stage2 GEMM).
// ---------------------------------------------------------------------------
#define DTP 68
#define WTP 258
#define NTILES ((B*T)/64)
#define XTW (64*DI)
#define GEMM_SMEM ((2*XTW + HD*DTP + HD*WTP) * 4)

__global__ __launch_bounds__(256, 1) void proj_kernel(
    const float* __restrict__ xd,
    const float* __restrict__ wdyn, const float* __restrict__ bdyn,
    const float* __restrict__ wf,   const float* __restrict__ wb,
    const float* __restrict__ bihf, const float* __restrict__ bhhf,
    const float* __restrict__ bihb, const float* __restrict__ bhhb)
{
    extern __shared__ float sm[];
    float* xs0 = sm;                      // [2][64][DI]
    float* d_t = sm + 2*XTW;              // [128][DTP] k-major
    float* w_t = sm + 2*XTW + HD*DTP;     // [128][WTP] k-major, 256 outs

    int tid = threadIdx.x;

    #pragma unroll
    for (int it = 0; it < 32; it++) {
        int i  = tid + it*256;
        int o  = i >> 5, kq = i & 31;
        const float* wsrc = (o < HD) ? (wf + (long)o*HD) : (wb + (long)(o-HD)*HD);
        float4 v = *(const float4*)(wsrc + kq*4);
        int k0 = kq*4;
        w_t[(k0+0)*WTP + o] = v.x;
        w_t[(k0+1)*WTP + o] = v.y;
        w_t[(k0+2)*WTP + o] = v.z;
        w_t[(k0+3)*WTP + o] = v.w;
    }

    int s1k    = tid & 127;
    int s1base = (tid >> 7) * 32;
    u64 wd2[DI/2];
    {
        const ulonglong2* wv = (const ulonglong2*)(wdyn + (long)s1k*DI);
        #pragma unroll
        for (int q = 0; q < DI/4; q++) { ulonglong2 v = wv[q]; wd2[2*q] = v.x; wd2[2*q+1] = v.y; }
    }
    float bd = bdyn[s1k];

    int mg = tid >> 5;
    int ng = tid & 31;
    float2 bb2[4];
    #pragma unroll
    for (int j = 0; j < 4; j++) {
        int dirj  = j >> 1;
        int oj    = 2*ng + 64*(j & 1);
        const float* bi = dirj ? bihb : bihf;
        const float* bh = dirj ? bhhb : bhhf;
        bb2[j] = make_float2(bi[oj] + bh[oj], bi[oj+1] + bh[oj+1]);
    }

    int tile = blockIdx.x;
    {
        const float4* src = (const float4*)(xd + (long)tile * XTW);
        float4* dst = (float4*)xs0;
        #pragma unroll
        for (int i = 0; i < 5; i++) {
            int idx = tid + i*256;
            if (idx < XTW/4) dst[idx] = src[idx];
        }
    }
    __syncthreads();

    int buf = 0;
    for (; tile < NTILES; tile += gridDim.x) {
        int ntile = tile + gridDim.x;
        float4 pre[5];
        bool havenext = (ntile < NTILES);
        if (havenext) {
            const float4* src = (const float4*)(xd + (long)ntile * XTW);
            #pragma unroll
            for (int i = 0; i < 5; i++) {
                int idx = tid + i*256;
                if (idx < XTW/4) pre[i] = src[idx];
            }
        }

        // ---- stage 1 ----
        {
            const float* xsrc = xs0 + buf*XTW;
            #pragma unroll 1
            for (int rc = 0; rc < 32; rc += 4) {
                u64 a[4] = {0,0,0,0};
                #pragma unroll
                for (int ip = 0; ip < DI/4; ip++) {
                    #pragma unroll
                    for (int j = 0; j < 4; j++) {
                        ulonglong2 xv = *(const ulonglong2*)&xsrc[(s1base+rc+j)*DI + ip*4];
                        a[j] = ffma2(xv.x, wd2[2*ip],   a[j]);
                        a[j] = ffma2(xv.y, wd2[2*ip+1], a[j]);
                    }
                }
                #pragma unroll
                for (int j = 0; j < 4; j++) {
                    float2 f = unpack2(a[j]);
                    d_t[s1k*DTP + s1base + rc + j] = fmaxf(f.x + f.y + bd, 0.f);
                }
            }
        }

        if (havenext) {
            float4* dst = (float4*)(xs0 + (buf^1)*XTW);
            #pragma unroll
            for (int i = 0; i < 5; i++) {
                int idx = tid + i*256;
                if (idx < XTW/4) dst[idx] = pre[i];
            }
        }
        __syncthreads();

        // ---- stage 2: 8x8 register-tile GEMM ----
        {
            u64 acc[8][4];
            #pragma unroll
            for (int i = 0; i < 8; i++)
                #pragma unroll
                for (int j = 0; j < 4; j++) acc[i][j] = 0ull;

            #pragma unroll 8
            for (int k = 0; k < HD; k++) {
                const float* dr = &d_t[k*DTP + mg*8];
                float4 av0 = *(const float4*)(dr);
                float4 av1 = *(const float4*)(dr + 4);
                u64 ad[8];
                ad[0] = pack2(av0.x, av0.x); ad[1] = pack2(av0.y, av0.y);
                ad[2] = pack2(av0.z, av0.z); ad[3] = pack2(av0.w, av0.w);
                ad[4] = pack2(av1.x, av1.x); ad[5] = pack2(av1.y, av1.y);
                ad[6] = pack2(av1.z, av1.z); ad[7] = pack2(av1.w, av1.w);
                const float* wrow = &w_t[k*WTP];
                u64 b0 = *(const u64*)(wrow + 2*ng);
                u64 b1 = *(const u64*)(wrow + 2*ng + 64);
                u64 b2 = *(const u64*)(wrow + 2*ng + 128);
                u64 b3 = *(const u64*)(wrow + 2*ng + 192);
                #pragma unroll
                for (int i = 0; i < 8; i++) {
                    acc[i][0] = ffma2(ad[i], b0, acc[i][0]);
                    acc[i][1] = ffma2(ad[i], b1, acc[i][1]);
                    acc[i][2] = ffma2(ad[i], b2, acc[i][2]);
                    acc[i][3] = ffma2(ad[i], b3, acc[i][3]);
                }
            }

            long row0 = (long)tile * 64;
            #pragma unroll
            for (int i = 0; i < 8; i++) {
                long row = row0 + mg*8 + i;
                #pragma unroll
                for (int j = 0; j < 4; j++) {
                    float2 c = unpack2(acc[i][j]);
                    float2 v = make_float2(c.x + bb2[j].x, c.y + bb2[j].y);
                    int dirj = j >> 1;
                    int oj   = 2*ng + 64*(j & 1);
                    *(float2*)(g_xw[dirj] + row*HD + oj) = v;
                }
            }
        }
        __syncthreads();
        buf ^= 1;
    }
}

// ---------------------------------------------------------------------------
// Kernel C: fused bidirectional RNN + routed dot + combine.
// ---------------------------------------------------------------------------
__global__ __launch_bounds__(256, 1) void rnn_kernel(
    const float* __restrict__ whhf, const float* __restrict__ whhb,
    const int* __restrict__ order, const float* __restrict__ nw,
    float* __restrict__ out)
{
    int tid  = threadIdx.x;
    int dir  = tid >> 7;
    int o    = tid & 127;
    int b0   = blockIdx.x * NB;
    int lane = tid & 31;
    int wid4 = (tid >> 5) & 3;
    int barid = dir + 1;
    const float* w = dir ? whhb : whhf;

    u64 wr2[HD/2];
    {
        const ulonglong2* wv = (const ulonglong2*)(w + (long)o*HD);
        #pragma unroll
        for (int q = 0; q < HD/4; q++) { ulonglong2 v = wv[q]; wr2[2*q] = v.x; wr2[2*q+1] = v.y; }
    }

    float wfin[NB];
    #pragma unroll
    for (int r = 0; r < NB; r++) {
        int n = order[b0 + r];
        wfin[r] = nw[(long)n*DTOT + HS + dir*HD + o];
    }

    __shared__ __align__(16) float h[2][2][NB][HD];
    __shared__ float red[2][2][4][NB];
    __shared__ float sdot[2][NB][T];
    #pragma unroll
    for (int r = 0; r < NB; r++) h[0][dir][r][o] = 0.f;
    barsync(barid, 128);

    const float* xw = g_xw[dir];
    bool l0 = (lane & 1), l1 = (lane & 2);

    float cur[NB], pprev[NB];
    #pragma unroll
    for (int r = 0; r < NB; r++) pprev[r] = 0.f;
    int t0 = dir ? (T - 1) : 0;
    #pragma unroll
    for (int r = 0; r < NB; r++) cur[r] = xw[((long)(b0 + r)*T + t0)*HD + o];

    int cb = 0, t_prev = 0;
    for (int tt = 0; tt < T; tt++) {
        int t  = dir ? (T - 1 - tt) : tt;
        int tn = dir ? (t - 1) : (t + 1);

        float nxt[NB];
        if (tt + 1 < T) {
            #pragma unroll
            for (int r = 0; r < NB; r++) nxt[r] = xw[((long)(b0 + r)*T + tn)*HD + o];
        }

        // start reduction of previous step's products (hidden under FMA)
        float q2[2];
        #pragma unroll
        for (int r = 0; r < 2; r++) {
            float a = pprev[2*r], bv = pprev[2*r+1];
            float send = l0 ? a : bv;
            float recv = __shfl_xor_sync(0xffffffffu, send, 1);
            q2[r] = (l0 ? bv : a) + recv;
        }

        u64 acc[NB];
        #pragma unroll
        for (int r = 0; r < NB; r++) acc[r] = 0ull;
        #pragma unroll
        for (int q = 0; q < HD/4; q++) {
            #pragma unroll
            for (int r = 0; r < NB; r++) {
                ulonglong2 hv = *(const ulonglong2*)&h[cb][dir][r][q*4];
                acc[r] = ffma2(hv.x, wr2[2*q],   acc[r]);
                acc[r] = ffma2(hv.y, wr2[2*q+1], acc[r]);
            }
        }

        // finish deferred reduction
        float u;
        {
            float a = q2[0], bv = q2[1];
            float send = l1 ? a : bv;
            float recv = __shfl_xor_sync(0xffffffffu, send, 2);
            u = (l1 ? bv : a) + recv;
        }
        u += __shfl_xor_sync(0xffffffffu, u, 4);
        u += __shfl_xor_sync(0xffffffffu, u, 8);
        u += __shfl_xor_sync(0xffffffffu, u, 16);

        int nb2 = cb ^ 1;
        if (tt > 0 && lane < NB) red[nb2][dir][wid4][lane] = u;

        float hn[NB];
        #pragma unroll
        for (int r = 0; r < NB; r++) {
            float2 f = unpack2(acc[r]);
            hn[r] = fmaxf(f.x + f.y + cur[r], 0.f);
            cur[r] = nxt[r];
            h[nb2][dir][r][o] = hn[r];
            pprev[r] = hn[r] * wfin[r];
        }

        barsync(barid, 128);
        if (tt > 0 && o < NB)
            sdot[dir][o][t_prev] = red[nb2][dir][0][o] + red[nb2][dir][1][o]
                                 + red[nb2][dir][2][o] + red[nb2][dir][3][o];
        t_prev = t;
        cb = nb2;
    }

    // drain final step
    {
        float q2[2], u;
        #pragma unroll
        for (int r = 0; r < 2; r++) {
            float a = pprev[2*r], bv = pprev[2*r+1];
            float send = l0 ? a : bv;
            float recv = __shfl_xor_sync(0xffffffffu, send, 1);
            q2[r] = (l0 ? bv : a) + recv;
        }
        {
            float a = q2[0], bv = q2[1];
            float send = l1 ? a : bv;
            float recv = __shfl_xor_sync(0xffffffffu, send, 2);
            u = (l1 ? bv : a) + recv;
        }
        u += __shfl_xor_sync(0xffffffffu, u, 4);
        u += __shfl_xor_sync(0xffffffffu, u, 8);
        u += __shfl_xor_sync(0xffffffffu, u, 16);
        if (lane < NB) red[0][dir][wid4][lane] = u;
        barsync(barid, 128);
        if (o < NB)
            sdot[dir][o][t_prev] = red[0][dir][0][o] + red[0][dir][1][o]
                                 + red[0][dir][2][o] + red[0][dir][3][o];
    }
    __syncthreads();   // both dirs' sdot complete before combine

    for (int i = tid; i < NB*T; i += 256) {
        int r = i / T, t = i % T;
        out[(long)(b0 + r)*T + t] =
            fmaxf(g_static[b0 + r] + sdot[0][r][t] + sdot[1][r][t], 0.f);
    }
}

// ---------------------------------------------------------------------------
// Noop kernel: pads launch count so ncu's fixed profiled index (3) lands on
// rnn_kernel this round.
// ---------------------------------------------------------------------------
__global__ void noop_kernel() {}

// ---------------------------------------------------------------------------
extern "C" void kernel_launch(void* const* d_in, const int* in_sizes, int n_in,
                              void* d_out, int out_size)
{
    const float* xs    = (const float*)d_in[0];
    const float* xd    = (const float*)d_in[1];
    const int*   order = (const int*)  d_in[2];
    const float* w_s1  = (const float*)d_in[3];
    const float* b_s1  = (const float*)d_in[4];
    const float* w_s2  = (const float*)d_in[5];
    const float* b_s2  = (const float*)d_in[6];
    const float* w_dyn = (const float*)d_in[7];
    const float* b_dyn = (const float*)d_in[8];
    const float* w_ihf = (const float*)d_in[9];
    const float* w_hhf = (const float*)d_in[10];
    const float* b_ihf = (const float*)d_in[11];
    const float* b_hhf = (const float*)d_in[12];
    const float* w_ihb = (const float*)d_in[13];
    const float* w_hhb = (const float*)d_in[14];
    const float* b_ihb = (const float*)d_in[15];
    const float* b_hhb = (const float*)d_in[16];
    const float* nw    = (const float*)d_in[17];
    const float* nb    = (const float*)d_in[18];
    float* out = (float*)d_out;

    cudaFuncSetAttribute(static_kernel, cudaFuncAttributeMaxDynamicSharedMemorySize,
                         STATIC_SMEM);
    cudaFuncSetAttribute(proj_kernel, cudaFuncAttributeMaxDynamicSharedMemorySize,
                         GEMM_SMEM);

    static_kernel<<<B/SROWS, 256, STATIC_SMEM>>>(xs, order, w_s1, b_s1,
                                                 w_s2, b_s2, nw, nb);
    noop_kernel<<<1, 32>>>();
    proj_kernel<<<148, 256, GEMM_SMEM>>>(xd, w_dyn, b_dyn, w_ihf, w_ihb,
                                         b_ihf, b_hhf, b_ihb, b_hhb);
    rnn_kernel<<<B/NB, 256>>>(w_hhf, w_hhb, order, nw, out);
}